// round 11
// baseline (speedup 1.0000x reference)
#include <cuda_runtime.h>
#include <cuda_bf16.h>
#include <cstdint>

#define BB 32
#define SS 16
#define DD 4096
#define HH 32
#define HDIM 128
#define MAXLEN 2048
#define NSPLIT 8
#define TCH 4   // tail-copy chunks per bh

// Scratch
__device__ float g_qkv[3][512 * 4096];        // projection outputs (25 MB)
__device__ float g_xc[3][512 * 4096];         // rna(tf32) X, permuted-k (25 MB)
__device__ float g_knew[BB * HH * SS * HDIM]; // roped new K rows (8.4 MB)
__device__ float g_vnew[BB * HH * SS * HDIM]; // new V rows (8.4 MB)
__device__ float g_pm[NSPLIT * BB * HH * SS];
__device__ float g_pl[NSPLIT * BB * HH * SS];
__device__ float g_pacc[NSPLIT * BB * HH * SS * HDIM];

__device__ __forceinline__ float to_tf32(float x) {
    uint32_t u;
    asm("cvt.rna.tf32.f32 %0, %1;" : "=r"(u) : "f"(x));
    return __uint_as_float(u);
}
__device__ __forceinline__ uint32_t smem_u32(const void* p) {
    uint32_t a;
    asm("{ .reg .u64 t; cvta.to.shared.u64 t, %1; cvt.u32.u64 %0, t; }" : "=r"(a) : "l"(p));
    return a;
}
// logical k held at permuted column c (within 8-groups: [0,4,1,5,2,6,3,7])
__device__ __forceinline__ int kperm(int c) {
    return (c & ~7) | ((c & 7) >> 1) | ((c & 1) << 2);
}

// ---------------------------------------------------------------------------
// Kernel 0: X -> g_xc[z][m][c] = rna(X[m][kperm(c)])
// ---------------------------------------------------------------------------
__global__ __launch_bounds__(256) void conv_x(
    const float* __restrict__ Q, const float* __restrict__ K, const float* __restrict__ V) {
    const int z = blockIdx.y;
    const float* X = (z == 0) ? Q : ((z == 1) ? K : V);
    int idx = blockIdx.x * 256 + threadIdx.x;
    if (idx >= 512 * 4096) return;
    int m = idx >> 12, c = idx & 4095;
    g_xc[z][idx] = to_tf32(X[(size_t)m * 4096 + kperm(c)]);
}

// ---------------------------------------------------------------------------
// Kernel 2: tf32 mma.sync GEMM, cp.async 3-stage (R9 config).
// A from g_xc (tf32, permuted, (m,k) stride 36, LDS.64 pairs). B from raw W,
// native (k,n) layout, stride 136, cvt.rna on fragment registers.
// BM=BN=128, BK=32, 8 warps, warp 64x32.
// ---------------------------------------------------------------------------
#define ASTRIDE 36
#define BSTRIDE 136
#define ATILEF (128 * ASTRIDE)
#define BTILEF (32 * BSTRIDE)
#define STAGEF (ATILEF + BTILEF)
#define GEMM_SMEM_BYTES (3 * STAGEF * 4)   // 107520

__global__ __launch_bounds__(256) void gemm_tf32(
    const float* __restrict__ w0, const float* __restrict__ w1, const float* __restrict__ w2) {
    extern __shared__ float sm[];
    const uint32_t sb = smem_u32(sm);
    const int z = blockIdx.z;
    const float* A = g_xc[z];
    const float* W = (z == 0) ? w0 : ((z == 1) ? w1 : w2);
    float* Cout = g_qkv[z];

    const int m0 = blockIdx.y * 128;
    const int n0 = blockIdx.x * 128;
    const int tid = threadIdx.x;
    const int wid = tid >> 5;
    const int lane = tid & 31;
    const int g = lane >> 2;
    const int t = lane & 3;
    const int warp_m = (wid & 1) * 64;
    const int warp_n = (wid >> 1) * 32;

    float c[4][4][4];
#pragma unroll
    for (int mf = 0; mf < 4; mf++)
#pragma unroll
        for (int nf = 0; nf < 4; nf++)
#pragma unroll
            for (int r = 0; r < 4; r++) c[mf][nf][r] = 0.f;

    auto copy_tile = [&](int s, int k0) {
#pragma unroll
        for (int j = 0; j < 4; j++) {
            int idx = tid + j * 256;
            int r = idx >> 3, c4 = idx & 7;
            uint32_t dst = sb + (uint32_t)(s * STAGEF + r * ASTRIDE + c4 * 4) * 4;
            const float* src = &A[(size_t)(m0 + r) * 4096 + k0 + c4 * 4];
            asm volatile("cp.async.cg.shared.global [%0], [%1], 16;" :: "r"(dst), "l"(src));
        }
#pragma unroll
        for (int j = 0; j < 4; j++) {
            int idx = tid + j * 256;
            int r = idx >> 5, c4 = idx & 31;
            uint32_t dst = sb + (uint32_t)(s * STAGEF + ATILEF + r * BSTRIDE + c4 * 4) * 4;
            const float* src = &W[(size_t)(k0 + r) * 4096 + n0 + c4 * 4];
            asm volatile("cp.async.cg.shared.global [%0], [%1], 16;" :: "r"(dst), "l"(src));
        }
        asm volatile("cp.async.commit_group;");
    };

    auto compute = [&](int s) {
        const float* As = sm + s * STAGEF;
        const float* Bs = As + ATILEF;
#pragma unroll
        for (int ks = 0; ks < 4; ks++) {
            const int kb = ks * 8;
            uint32_t a[4][4], b[4][2];
#pragma unroll
            for (int mf = 0; mf < 4; mf++) {
                int r0 = warp_m + mf * 16 + g;
                uint2 lo = *(const uint2*)&As[r0 * ASTRIDE + kb + 2 * t];
                uint2 hi = *(const uint2*)&As[(r0 + 8) * ASTRIDE + kb + 2 * t];
                a[mf][0] = lo.x; a[mf][1] = hi.x; a[mf][2] = lo.y; a[mf][3] = hi.y;
            }
#pragma unroll
            for (int nf = 0; nf < 4; nf++) {
                int n = warp_n + nf * 8 + g;
                b[nf][0] = __float_as_uint(to_tf32(Bs[(kb + t) * BSTRIDE + n]));
                b[nf][1] = __float_as_uint(to_tf32(Bs[(kb + t + 4) * BSTRIDE + n]));
            }
#pragma unroll
            for (int mf = 0; mf < 4; mf++)
#pragma unroll
                for (int nf = 0; nf < 4; nf++) {
                    asm volatile(
                        "mma.sync.aligned.m16n8k8.row.col.f32.tf32.tf32.f32 "
                        "{%0,%1,%2,%3}, {%4,%5,%6,%7}, {%8,%9}, {%0,%1,%2,%3};"
                        : "+f"(c[mf][nf][0]), "+f"(c[mf][nf][1]),
                          "+f"(c[mf][nf][2]), "+f"(c[mf][nf][3])
                        : "r"(a[mf][0]), "r"(a[mf][1]), "r"(a[mf][2]), "r"(a[mf][3]),
                          "r"(b[nf][0]), "r"(b[nf][1]));
                }
        }
    };

    copy_tile(0, 0);
    copy_tile(1, 32);

    for (int it = 0; it < 128; ++it) {
        if (it < 126)
            asm volatile("cp.async.wait_group 1;");
        else
            asm volatile("cp.async.wait_group 0;");
        __syncthreads();
        compute(it % 3);
        if (it + 2 < 128) copy_tile((it + 2) % 3, (it + 2) * 32);
    }

#pragma unroll
    for (int mf = 0; mf < 4; mf++) {
        int row = m0 + warp_m + mf * 16 + g;
#pragma unroll
        for (int nf = 0; nf < 4; nf++) {
            int col = n0 + warp_n + nf * 8 + t * 2;
            *(float2*)&Cout[(size_t)row * 4096 + col] =
                make_float2(c[mf][nf][0], c[mf][nf][1]);
            *(float2*)&Cout[(size_t)(row + 8) * 4096 + col] =
                make_float2(c[mf][nf][2], c[mf][nf][3]);
        }
    }
}

// ---------------------------------------------------------------------------
// Kernel 3: RoPE q in place; rope k / copy v -> okc/ovc rows AND g_knew/g_vnew
// ---------------------------------------------------------------------------
__global__ void rope_scatter(const float* __restrict__ emb, const int* __restrict__ Cp,
                             float* __restrict__ okc, float* __restrict__ ovc) {
    int idx = blockIdx.x * blockDim.x + threadIdx.x;
    if (idx >= BB * SS * HH * 64) return;
    int e = idx & 63;
    int h = (idx >> 6) & 31;
    int s = (idx >> 11) & 15;
    int b = idx >> 15;
    int Cv = Cp[0];

    float c = emb[s * HDIM + e];
    float sn = emb[SS * HDIM + s * HDIM + e];
    int row = b * SS + s;
    int c1 = h * HDIM + e;
    int c2 = c1 + 64;

    float* qp = g_qkv[0];
    float x1 = qp[row * DD + c1], x2 = qp[row * DD + c2];
    qp[row * DD + c1] = x1 * c - x2 * sn;
    qp[row * DD + c2] = x2 * c + x1 * sn;

    const float* kp = g_qkv[1];
    x1 = kp[row * DD + c1];
    x2 = kp[row * DD + c2];
    float k1 = x1 * c - x2 * sn;
    float k2 = x2 * c + x1 * sn;
    int o = ((b * HH + h) * MAXLEN + (Cv + s)) * HDIM;
    int on = ((b * HH + h) * SS + s) * HDIM;
    okc[o + e] = k1;
    okc[o + e + 64] = k2;
    g_knew[on + e] = k1;
    g_knew[on + e + 64] = k2;

    const float* vp = g_qkv[2];
    float v1 = vp[row * DD + c1];
    float v2 = vp[row * DD + c2];
    ovc[o + e] = v1;
    ovc[o + e + 64] = v2;
    g_vnew[on + e] = v1;
    g_vnew[on + e + 64] = v2;
}

// ---------------------------------------------------------------------------
// Kernel 4: split-K flash attention partials + FULL cache copy duty.
//  - chunks [0, NSPLIT): attention over keys; rows [0,C) of each tile are
//    stored to okc/ovc as copy duty (R9 scheme)
//  - chunks [NSPLIT, NSPLIT+TCH): dedicated tail-copy blocks for rows
//    [L, MAXLEN) — fixed work, retire fast, co-scheduled with attn blocks
//  - rows [C,L): written by rope_scatter
// ---------------------------------------------------------------------------
#define QF (SS * 132)                 // 2112 floats
#define KVF (32 * 132)                // 4224 floats per k/v buffer
#define ATTN_SMEM_F (QF + 4 * KVF + 4 * 4 * 32)
#define ATTN_SMEM_BYTES (ATTN_SMEM_F * 4)   // 78080

__global__ __launch_bounds__(128) void attn_partial(
    const float* __restrict__ Kcin, const float* __restrict__ Vcin,
    const int* __restrict__ Cp,
    float* __restrict__ okc, float* __restrict__ ovc) {
    extern __shared__ float dsm[];
    float* q_s = dsm;                       // [16][132]
    float* p_s = dsm + QF + 4 * KVF;        // [4][4][32]
    const uint32_t sb = smem_u32(dsm);

    const int tid = threadIdx.x;
    const int w = tid >> 5;
    const int lane = tid & 31;
    const int bh = blockIdx.x;
    const int chunk = blockIdx.y;
    const int b = bh >> 5;
    const int h = bh & 31;
    const int Cv = Cp[0];
    const int L = Cv + SS;

    const float* kold = Kcin + (size_t)bh * MAXLEN * HDIM;
    const float* vold = Vcin + (size_t)bh * MAXLEN * HDIM;
    float* kout = okc + (size_t)bh * MAXLEN * HDIM;
    float* vout = ovc + (size_t)bh * MAXLEN * HDIM;

    // ---- dedicated tail-copy blocks ----
    if (chunk >= NSPLIT) {
        const int tc = chunk - NSPLIT;
        const int rows_tail = MAXLEN - L;
        const int tsz = (rows_tail + TCH - 1) / TCH;
        const int tstart = L + tc * tsz;
        const int tend = min(tstart + tsz, MAXLEN);
        const int nrow = tend - tstart;
        for (int i = tid; i < nrow * 32; i += 128) {
            int r = i >> 5, c4 = i & 31;
            size_t off = (size_t)(tstart + r) * HDIM + c4 * 4;
            float4 a = __ldcs((const float4*)&kold[off]);
            float4 v = __ldcs((const float4*)&vold[off]);
            __stcs((float4*)&kout[off], a);
            __stcs((float4*)&vout[off], v);
        }
        return;
    }

    const int csz = (((L + NSPLIT - 1) / NSPLIT) + 31) & ~31;
    const int kstart = chunk * csz;
    const int kend = min(kstart + csz, L);
    const int pbase = (chunk * BB * HH + bh) * SS;

    if (kstart >= kend) {
        for (int i = tid; i < SS * HDIM; i += 128) g_pacc[pbase * HDIM + i] = 0.f;
        if (tid < SS) {
            g_pm[pbase + tid] = -1e30f;
            g_pl[pbase + tid] = 0.f;
        }
        return;
    }

    // q tile
    const float* qbase = g_qkv[0] + (b * SS) * DD + h * HDIM;
    for (int i = tid; i < SS * 32; i += 128) {
        int r = i >> 5, c4 = i & 31;
        *(float4*)&q_s[r * 132 + c4 * 4] = *(const float4*)&qbase[r * DD + c4 * 4];
    }

    const float* knew = g_knew + (size_t)bh * SS * HDIM;
    const float* vnew = g_vnew + (size_t)bh * SS * HDIM;

    auto load_tile = [&](int base, int buf) {
        uint32_t kdst = sb + (uint32_t)(QF + buf * 2 * KVF) * 4;
        uint32_t vdst = kdst + (uint32_t)KVF * 4;
#pragma unroll
        for (int j = 0; j < 8; j++) {
            int idx = tid + j * 128;
            int r = idx >> 5, c4 = idx & 31;
            int kpos = base + r;
            uint32_t off = (uint32_t)(r * 132 + c4 * 4) * 4;
            if (kpos < Cv) {
                const float* sk = &kold[(size_t)kpos * HDIM + c4 * 4];
                const float* sv = &vold[(size_t)kpos * HDIM + c4 * 4];
                asm volatile("cp.async.cg.shared.global [%0], [%1], 16;" :: "r"(kdst + off), "l"(sk));
                asm volatile("cp.async.cg.shared.global [%0], [%1], 16;" :: "r"(vdst + off), "l"(sv));
            } else if (kpos < kend) {
                const float* sk = &knew[(size_t)(kpos - Cv) * HDIM + c4 * 4];
                const float* sv = &vnew[(size_t)(kpos - Cv) * HDIM + c4 * 4];
                asm volatile("cp.async.cg.shared.global [%0], [%1], 16;" :: "r"(kdst + off), "l"(sk));
                asm volatile("cp.async.cg.shared.global [%0], [%1], 16;" :: "r"(vdst + off), "l"(sv));
            } else {
                float* vp = dsm + QF + (buf * 2 + 1) * KVF + r * 132 + c4 * 4;
                *(float4*)vp = make_float4(0.f, 0.f, 0.f, 0.f);
            }
        }
        asm volatile("cp.async.commit_group;");
    };

    float m[4], l[4], acc[4][4];
#pragma unroll
    for (int qi = 0; qi < 4; qi++) {
        m[qi] = -1e30f;
        l[qi] = 0.f;
#pragma unroll
        for (int d = 0; d < 4; d++) acc[qi][d] = 0.f;
    }

    const int nt = (kend - kstart + 31) / 32;
    load_tile(kstart, 0);

    for (int tix = 0; tix < nt; tix++) {
        asm volatile("cp.async.wait_group 0;");
        __syncthreads();
        const int buf = tix & 1;
        if (tix + 1 < nt) load_tile(kstart + (tix + 1) * 32, buf ^ 1);

        const float* k_s = dsm + QF + buf * 2 * KVF;
        const float* v_s = k_s + KVF;
        const int base = kstart + tix * 32;

        // copy duty: write old-cache rows of this tile to the output caches
        if (base < Cv) {
#pragma unroll
            for (int j = 0; j < 8; j++) {
                int idx = tid + j * 128;
                int r = idx >> 5, c4 = idx & 31;
                int kpos = base + r;
                if (kpos < Cv) {
                    float4 kv = *(const float4*)&k_s[r * 132 + c4 * 4];
                    float4 vv = *(const float4*)&v_s[r * 132 + c4 * 4];
                    __stcs((float4*)&kout[(size_t)kpos * HDIM + c4 * 4], kv);
                    __stcs((float4*)&vout[(size_t)kpos * HDIM + c4 * 4], vv);
                }
            }
        }

        float sc[4] = {0.f, 0.f, 0.f, 0.f};
#pragma unroll 8
        for (int d4 = 0; d4 < 32; d4++) {
            float4 kv = *(const float4*)&k_s[lane * 132 + d4 * 4];
#pragma unroll
            for (int qi = 0; qi < 4; qi++) {
                float4 qv = *(const float4*)&q_s[(w * 4 + qi) * 132 + d4 * 4];
                sc[qi] += qv.x * kv.x + qv.y * kv.y + qv.z * kv.z + qv.w * kv.w;
            }
        }

        int kpos = base + lane;
#pragma unroll
        for (int qi = 0; qi < 4; qi++) {
            bool valid = (kpos < kend) && (kpos <= Cv + (w * 4 + qi));
            float sv = valid ? sc[qi] * 0.08838834764831845f : -1e30f;
            float tm = sv;
#pragma unroll
            for (int o = 16; o > 0; o >>= 1) tm = fmaxf(tm, __shfl_xor_sync(0xffffffffu, tm, o));
            float mn = fmaxf(m[qi], tm);
            float corr = __expf(m[qi] - mn);
            float p = valid ? __expf(sv - mn) : 0.f;
            float rs = p;
#pragma unroll
            for (int o = 16; o > 0; o >>= 1) rs += __shfl_xor_sync(0xffffffffu, rs, o);
            l[qi] = l[qi] * corr + rs;
            m[qi] = mn;
#pragma unroll
            for (int d = 0; d < 4; d++) acc[qi][d] *= corr;
            p_s[(w * 4 + qi) * 32 + lane] = p;
        }
        __syncwarp();

#pragma unroll 4
        for (int j = 0; j < 32; j++) {
            float4 vv = *(const float4*)&v_s[j * 132 + lane * 4];
#pragma unroll
            for (int qi = 0; qi < 4; qi++) {
                float p = p_s[(w * 4 + qi) * 32 + j];
                acc[qi][0] += p * vv.x;
                acc[qi][1] += p * vv.y;
                acc[qi][2] += p * vv.z;
                acc[qi][3] += p * vv.w;
            }
        }
    }

#pragma unroll
    for (int qi = 0; qi < 4; qi++) {
        int s = w * 4 + qi;
        *(float4*)&g_pacc[(pbase + s) * HDIM + lane * 4] =
            make_float4(acc[qi][0], acc[qi][1], acc[qi][2], acc[qi][3]);
        if (lane == 0) {
            g_pm[pbase + s] = m[qi];
            g_pl[pbase + s] = l[qi];
        }
    }
}

// ---------------------------------------------------------------------------
// Kernel 5: combine partials -> out
// ---------------------------------------------------------------------------
__global__ __launch_bounds__(128) void attn_combine(float* __restrict__ out) {
    const int bh = blockIdx.x;
    const int b = bh >> 5;
    const int h = bh & 31;
    const int d = threadIdx.x;

    for (int s = 0; s < SS; s++) {
        float mv[NSPLIT];
        float M = -1e30f;
#pragma unroll
        for (int c = 0; c < NSPLIT; c++) {
            mv[c] = g_pm[(c * BB * HH + bh) * SS + s];
            M = fmaxf(M, mv[c]);
        }
        float denom = 0.f, o = 0.f;
#pragma unroll
        for (int c = 0; c < NSPLIT; c++) {
            float wgt = __expf(mv[c] - M);
            denom += wgt * g_pl[(c * BB * HH + bh) * SS + s];
            o += wgt * g_pacc[((c * BB * HH + bh) * SS + s) * HDIM + d];
        }
        out[(b * SS + s) * DD + h * HDIM + d] = o / denom;
    }
}

// ---------------------------------------------------------------------------
extern "C" void kernel_launch(void* const* d_in, const int* in_sizes, int n_in,
                              void* d_out, int out_size) {
    const float* Q = (const float*)d_in[0];
    const float* K = (const float*)d_in[1];
    const float* V = (const float*)d_in[2];
    const float* Kcache = (const float*)d_in[3];
    const float* Vcache = (const float*)d_in[4];
    const float* w0 = (const float*)d_in[5];
    const float* w1 = (const float*)d_in[6];
    const float* w2 = (const float*)d_in[7];
    const float* emb = (const float*)d_in[8];
    const int* Cp = (const int*)d_in[9];

    float* out = (float*)d_out;
    float* okc = out + (size_t)BB * SS * DD;
    float* ovc = okc + (size_t)BB * HH * MAXLEN * HDIM;

    static bool init = false;
    if (!init) {
        init = true;
        cudaFuncSetAttribute(gemm_tf32, cudaFuncAttributeMaxDynamicSharedMemorySize,
                             GEMM_SMEM_BYTES);
        cudaFuncSetAttribute(attn_partial, cudaFuncAttributeMaxDynamicSharedMemorySize,
                             ATTN_SMEM_BYTES);
    }

    dim3 gx((512 * 4096 + 255) / 256, 3);
    conv_x<<<gx, 256>>>(Q, K, V);

    dim3 gg(4096 / 128, 512 / 128, 3);
    gemm_tf32<<<gg, 256, GEMM_SMEM_BYTES>>>(w0, w1, w2);

    rope_scatter<<<(BB * SS * HH * 64 + 255) / 256, 256>>>(emb, Cp, okc, ovc);

    dim3 ga(BB * HH, NSPLIT + TCH);
    attn_partial<<<ga, 128, ATTN_SMEM_BYTES>>>(Kcache, Vcache, Cp, okc, ovc);
    attn_combine<<<BB * HH, 128>>>(out);
}

// round 12
// speedup vs baseline: 1.2083x; 1.2083x over previous
#include <cuda_runtime.h>
#include <cuda_bf16.h>
#include <cstdint>

#define BB 32
#define SS 16
#define DD 4096
#define HH 32
#define HDIM 128
#define MAXLEN 2048
#define NSPLIT 8

// Scratch
__device__ float g_qkv[3][512 * 4096];        // projection outputs (25 MB)
__device__ float g_xc[3][512 * 4096];         // rna(tf32) X, permuted-k (25 MB)
__device__ float g_knew[BB * HH * SS * HDIM]; // roped new K rows (8.4 MB)
__device__ float g_vnew[BB * HH * SS * HDIM]; // new V rows (8.4 MB)
__device__ float g_pm[NSPLIT * BB * HH * SS];
__device__ float g_pl[NSPLIT * BB * HH * SS];
__device__ float g_pacc[NSPLIT * BB * HH * SS * HDIM];

__device__ __forceinline__ float to_tf32(float x) {
    uint32_t u;
    asm("cvt.rna.tf32.f32 %0, %1;" : "=r"(u) : "f"(x));
    return __uint_as_float(u);
}
__device__ __forceinline__ uint32_t smem_u32(const void* p) {
    uint32_t a;
    asm("{ .reg .u64 t; cvta.to.shared.u64 t, %1; cvt.u32.u64 %0, t; }" : "=r"(a) : "l"(p));
    return a;
}
// logical k held at permuted column c (within 8-groups: [0,4,1,5,2,6,3,7])
__device__ __forceinline__ int kperm(int c) {
    return (c & ~7) | ((c & 7) >> 1) | ((c & 1) << 2);
}

// ---------------------------------------------------------------------------
// Kernel 0: X -> g_xc[z][m][c] = rna(X[m][kperm(c)])
// ---------------------------------------------------------------------------
__global__ __launch_bounds__(256) void conv_x(
    const float* __restrict__ Q, const float* __restrict__ K, const float* __restrict__ V) {
    const int z = blockIdx.y;
    const float* X = (z == 0) ? Q : ((z == 1) ? K : V);
    int idx = blockIdx.x * 256 + threadIdx.x;
    if (idx >= 512 * 4096) return;
    int m = idx >> 12, c = idx & 4095;
    g_xc[z][idx] = to_tf32(X[(size_t)m * 4096 + kperm(c)]);
}

// ---------------------------------------------------------------------------
// Kernel 1 (side stream, co-scheduled with gemm): copy tail rows [L, MAXLEN).
// 128-thread blocks so they co-reside with gemm CTAs (register budget).
// Rows [0,C) are copied by attn_partial; rows [C,L) by rope_scatter.
// ---------------------------------------------------------------------------
__global__ __launch_bounds__(128) void copy_tail(
    const float4* __restrict__ kc, const float4* __restrict__ vc,
    float4* __restrict__ okc, float4* __restrict__ ovc,
    const int* __restrict__ Cp) {
    const int L = Cp[0] + SS;
    const int rows_tail = MAXLEN - L;
    const int per_bh = rows_tail * 32;          // float4 per (b,h)
    const int total = BB * HH * per_bh;
    int stride = gridDim.x * blockDim.x;
    for (int i = blockIdx.x * blockDim.x + threadIdx.x; i < total; i += stride) {
        int bh = i / per_bh;
        int rem = i - bh * per_bh;
        int pos = L + (rem >> 5);
        int c4 = rem & 31;
        size_t off = ((size_t)bh * MAXLEN + pos) * 32 + c4;
        float4 a = __ldcs(&kc[off]);
        float4 b = __ldcs(&vc[off]);
        __stcs(&okc[off], a);
        __stcs(&ovc[off], b);
    }
}

// ---------------------------------------------------------------------------
// Kernel 2: tf32 mma.sync GEMM, cp.async 3-stage. A from g_xc (tf32,permuted,
// (m,k) stride 36, LDS.64 pairs). B from raw W, native (k,n) layout, stride
// 136, cvt.rna on fragment registers. BM=BN=128, BK=32, 8 warps, warp 64x32.
// ---------------------------------------------------------------------------
#define ASTRIDE 36
#define BSTRIDE 136
#define ATILEF (128 * ASTRIDE)
#define BTILEF (32 * BSTRIDE)
#define STAGEF (ATILEF + BTILEF)
#define GEMM_SMEM_BYTES (3 * STAGEF * 4)   // 107520

__global__ __launch_bounds__(256) void gemm_tf32(
    const float* __restrict__ w0, const float* __restrict__ w1, const float* __restrict__ w2) {
    extern __shared__ float sm[];
    const uint32_t sb = smem_u32(sm);
    const int z = blockIdx.z;
    const float* A = g_xc[z];
    const float* W = (z == 0) ? w0 : ((z == 1) ? w1 : w2);
    float* Cout = g_qkv[z];

    const int m0 = blockIdx.y * 128;
    const int n0 = blockIdx.x * 128;
    const int tid = threadIdx.x;
    const int wid = tid >> 5;
    const int lane = tid & 31;
    const int g = lane >> 2;
    const int t = lane & 3;
    const int warp_m = (wid & 1) * 64;
    const int warp_n = (wid >> 1) * 32;

    float c[4][4][4];
#pragma unroll
    for (int mf = 0; mf < 4; mf++)
#pragma unroll
        for (int nf = 0; nf < 4; nf++)
#pragma unroll
            for (int r = 0; r < 4; r++) c[mf][nf][r] = 0.f;

    auto copy_tile = [&](int s, int k0) {
#pragma unroll
        for (int j = 0; j < 4; j++) {
            int idx = tid + j * 256;
            int r = idx >> 3, c4 = idx & 7;
            uint32_t dst = sb + (uint32_t)(s * STAGEF + r * ASTRIDE + c4 * 4) * 4;
            const float* src = &A[(size_t)(m0 + r) * 4096 + k0 + c4 * 4];
            asm volatile("cp.async.cg.shared.global [%0], [%1], 16;" :: "r"(dst), "l"(src));
        }
#pragma unroll
        for (int j = 0; j < 4; j++) {
            int idx = tid + j * 256;
            int r = idx >> 5, c4 = idx & 31;
            uint32_t dst = sb + (uint32_t)(s * STAGEF + ATILEF + r * BSTRIDE + c4 * 4) * 4;
            const float* src = &W[(size_t)(k0 + r) * 4096 + n0 + c4 * 4];
            asm volatile("cp.async.cg.shared.global [%0], [%1], 16;" :: "r"(dst), "l"(src));
        }
        asm volatile("cp.async.commit_group;");
    };

    auto compute = [&](int s) {
        const float* As = sm + s * STAGEF;
        const float* Bs = As + ATILEF;
#pragma unroll
        for (int ks = 0; ks < 4; ks++) {
            const int kb = ks * 8;
            uint32_t a[4][4], b[4][2];
#pragma unroll
            for (int mf = 0; mf < 4; mf++) {
                int r0 = warp_m + mf * 16 + g;
                uint2 lo = *(const uint2*)&As[r0 * ASTRIDE + kb + 2 * t];
                uint2 hi = *(const uint2*)&As[(r0 + 8) * ASTRIDE + kb + 2 * t];
                a[mf][0] = lo.x; a[mf][1] = hi.x; a[mf][2] = lo.y; a[mf][3] = hi.y;
            }
#pragma unroll
            for (int nf = 0; nf < 4; nf++) {
                int n = warp_n + nf * 8 + g;
                b[nf][0] = __float_as_uint(to_tf32(Bs[(kb + t) * BSTRIDE + n]));
                b[nf][1] = __float_as_uint(to_tf32(Bs[(kb + t + 4) * BSTRIDE + n]));
            }
#pragma unroll
            for (int mf = 0; mf < 4; mf++)
#pragma unroll
                for (int nf = 0; nf < 4; nf++) {
                    asm volatile(
                        "mma.sync.aligned.m16n8k8.row.col.f32.tf32.tf32.f32 "
                        "{%0,%1,%2,%3}, {%4,%5,%6,%7}, {%8,%9}, {%0,%1,%2,%3};"
                        : "+f"(c[mf][nf][0]), "+f"(c[mf][nf][1]),
                          "+f"(c[mf][nf][2]), "+f"(c[mf][nf][3])
                        : "r"(a[mf][0]), "r"(a[mf][1]), "r"(a[mf][2]), "r"(a[mf][3]),
                          "r"(b[nf][0]), "r"(b[nf][1]));
                }
        }
    };

    copy_tile(0, 0);
    copy_tile(1, 32);

    for (int it = 0; it < 128; ++it) {
        if (it < 126)
            asm volatile("cp.async.wait_group 1;");
        else
            asm volatile("cp.async.wait_group 0;");
        __syncthreads();
        compute(it % 3);
        if (it + 2 < 128) copy_tile((it + 2) % 3, (it + 2) * 32);
    }

#pragma unroll
    for (int mf = 0; mf < 4; mf++) {
        int row = m0 + warp_m + mf * 16 + g;
#pragma unroll
        for (int nf = 0; nf < 4; nf++) {
            int col = n0 + warp_n + nf * 8 + t * 2;
            *(float2*)&Cout[(size_t)row * 4096 + col] =
                make_float2(c[mf][nf][0], c[mf][nf][1]);
            *(float2*)&Cout[(size_t)(row + 8) * 4096 + col] =
                make_float2(c[mf][nf][2], c[mf][nf][3]);
        }
    }
}

// ---------------------------------------------------------------------------
// Kernel 3: RoPE q in place; rope k / copy v -> okc/ovc rows AND g_knew/g_vnew
// ---------------------------------------------------------------------------
__global__ void rope_scatter(const float* __restrict__ emb, const int* __restrict__ Cp,
                             float* __restrict__ okc, float* __restrict__ ovc) {
    int idx = blockIdx.x * blockDim.x + threadIdx.x;
    if (idx >= BB * SS * HH * 64) return;
    int e = idx & 63;
    int h = (idx >> 6) & 31;
    int s = (idx >> 11) & 15;
    int b = idx >> 15;
    int Cv = Cp[0];

    float c = emb[s * HDIM + e];
    float sn = emb[SS * HDIM + s * HDIM + e];
    int row = b * SS + s;
    int c1 = h * HDIM + e;
    int c2 = c1 + 64;

    float* qp = g_qkv[0];
    float x1 = qp[row * DD + c1], x2 = qp[row * DD + c2];
    qp[row * DD + c1] = x1 * c - x2 * sn;
    qp[row * DD + c2] = x2 * c + x1 * sn;

    const float* kp = g_qkv[1];
    x1 = kp[row * DD + c1];
    x2 = kp[row * DD + c2];
    float k1 = x1 * c - x2 * sn;
    float k2 = x2 * c + x1 * sn;
    int o = ((b * HH + h) * MAXLEN + (Cv + s)) * HDIM;
    int on = ((b * HH + h) * SS + s) * HDIM;
    okc[o + e] = k1;
    okc[o + e + 64] = k2;
    g_knew[on + e] = k1;
    g_knew[on + e + 64] = k2;

    const float* vp = g_qkv[2];
    float v1 = vp[row * DD + c1];
    float v2 = vp[row * DD + c2];
    ovc[o + e] = v1;
    ovc[o + e + 64] = v2;
    g_vnew[on + e] = v1;
    g_vnew[on + e + 64] = v2;
}

// ---------------------------------------------------------------------------
// Kernel 4: split-K flash attention partials + copy duty for rows [0,C).
// K/V read from INPUT caches (pos < C) / g_knew,g_vnew (pos >= C) via
// double-buffered cp.async; after each tile lands in smem, rows with
// kpos < C are stored to okc/ovc (the chunks tile [0,L) disjointly).
// ---------------------------------------------------------------------------
#define QF (SS * 132)                 // 2112 floats
#define KVF (32 * 132)                // 4224 floats per k/v buffer
#define ATTN_SMEM_F (QF + 4 * KVF + 4 * 4 * 32)
#define ATTN_SMEM_BYTES (ATTN_SMEM_F * 4)   // 78080

__global__ __launch_bounds__(128) void attn_partial(
    const float* __restrict__ Kcin, const float* __restrict__ Vcin,
    const int* __restrict__ Cp,
    float* __restrict__ okc, float* __restrict__ ovc) {
    extern __shared__ float dsm[];
    float* q_s = dsm;                       // [16][132]
    float* p_s = dsm + QF + 4 * KVF;        // [4][4][32]
    const uint32_t sb = smem_u32(dsm);

    const int tid = threadIdx.x;
    const int w = tid >> 5;
    const int lane = tid & 31;
    const int bh = blockIdx.x;
    const int chunk = blockIdx.y;
    const int b = bh >> 5;
    const int h = bh & 31;
    const int Cv = Cp[0];
    const int L = Cv + SS;
    const int csz = (((L + NSPLIT - 1) / NSPLIT) + 31) & ~31;
    const int kstart = chunk * csz;
    const int kend = min(kstart + csz, L);
    const int pbase = (chunk * BB * HH + bh) * SS;

    if (kstart >= kend) {
        for (int i = tid; i < SS * HDIM; i += 128) g_pacc[pbase * HDIM + i] = 0.f;
        if (tid < SS) {
            g_pm[pbase + tid] = -1e30f;
            g_pl[pbase + tid] = 0.f;
        }
        return;
    }

    // q tile
    const float* qbase = g_qkv[0] + (b * SS) * DD + h * HDIM;
    for (int i = tid; i < SS * 32; i += 128) {
        int r = i >> 5, c4 = i & 31;
        *(float4*)&q_s[r * 132 + c4 * 4] = *(const float4*)&qbase[r * DD + c4 * 4];
    }

    const float* kold = Kcin + (size_t)bh * MAXLEN * HDIM;
    const float* vold = Vcin + (size_t)bh * MAXLEN * HDIM;
    const float* knew = g_knew + (size_t)bh * SS * HDIM;
    const float* vnew = g_vnew + (size_t)bh * SS * HDIM;
    float* kout = okc + (size_t)bh * MAXLEN * HDIM;
    float* vout = ovc + (size_t)bh * MAXLEN * HDIM;

    auto load_tile = [&](int base, int buf) {
        uint32_t kdst = sb + (uint32_t)(QF + buf * 2 * KVF) * 4;
        uint32_t vdst = kdst + (uint32_t)KVF * 4;
#pragma unroll
        for (int j = 0; j < 8; j++) {
            int idx = tid + j * 128;
            int r = idx >> 5, c4 = idx & 31;
            int kpos = base + r;
            uint32_t off = (uint32_t)(r * 132 + c4 * 4) * 4;
            if (kpos < Cv) {
                const float* sk = &kold[(size_t)kpos * HDIM + c4 * 4];
                const float* sv = &vold[(size_t)kpos * HDIM + c4 * 4];
                asm volatile("cp.async.cg.shared.global [%0], [%1], 16;" :: "r"(kdst + off), "l"(sk));
                asm volatile("cp.async.cg.shared.global [%0], [%1], 16;" :: "r"(vdst + off), "l"(sv));
            } else if (kpos < kend) {
                const float* sk = &knew[(size_t)(kpos - Cv) * HDIM + c4 * 4];
                const float* sv = &vnew[(size_t)(kpos - Cv) * HDIM + c4 * 4];
                asm volatile("cp.async.cg.shared.global [%0], [%1], 16;" :: "r"(kdst + off), "l"(sk));
                asm volatile("cp.async.cg.shared.global [%0], [%1], 16;" :: "r"(vdst + off), "l"(sv));
            } else {
                float* vp = dsm + QF + (buf * 2 + 1) * KVF + r * 132 + c4 * 4;
                *(float4*)vp = make_float4(0.f, 0.f, 0.f, 0.f);
            }
        }
        asm volatile("cp.async.commit_group;");
    };

    float m[4], l[4], acc[4][4];
#pragma unroll
    for (int qi = 0; qi < 4; qi++) {
        m[qi] = -1e30f;
        l[qi] = 0.f;
#pragma unroll
        for (int d = 0; d < 4; d++) acc[qi][d] = 0.f;
    }

    const int nt = (kend - kstart + 31) / 32;
    load_tile(kstart, 0);

    for (int tix = 0; tix < nt; tix++) {
        asm volatile("cp.async.wait_group 0;");
        __syncthreads();
        const int buf = tix & 1;
        if (tix + 1 < nt) load_tile(kstart + (tix + 1) * 32, buf ^ 1);

        const float* k_s = dsm + QF + buf * 2 * KVF;
        const float* v_s = k_s + KVF;
        const int base = kstart + tix * 32;

        // copy duty: write old-cache rows of this tile to the output caches
        if (base < Cv) {
#pragma unroll
            for (int j = 0; j < 8; j++) {
                int idx = tid + j * 128;
                int r = idx >> 5, c4 = idx & 31;
                int kpos = base + r;
                if (kpos < Cv) {
                    float4 kv = *(const float4*)&k_s[r * 132 + c4 * 4];
                    float4 vv = *(const float4*)&v_s[r * 132 + c4 * 4];
                    __stcs((float4*)&kout[(size_t)kpos * HDIM + c4 * 4], kv);
                    __stcs((float4*)&vout[(size_t)kpos * HDIM + c4 * 4], vv);
                }
            }
        }

        float sc[4] = {0.f, 0.f, 0.f, 0.f};
#pragma unroll 8
        for (int d4 = 0; d4 < 32; d4++) {
            float4 kv = *(const float4*)&k_s[lane * 132 + d4 * 4];
#pragma unroll
            for (int qi = 0; qi < 4; qi++) {
                float4 qv = *(const float4*)&q_s[(w * 4 + qi) * 132 + d4 * 4];
                sc[qi] += qv.x * kv.x + qv.y * kv.y + qv.z * kv.z + qv.w * kv.w;
            }
        }

        int kpos = base + lane;
#pragma unroll
        for (int qi = 0; qi < 4; qi++) {
            bool valid = (kpos < kend) && (kpos <= Cv + (w * 4 + qi));
            float sv = valid ? sc[qi] * 0.08838834764831845f : -1e30f;
            float tm = sv;
#pragma unroll
            for (int o = 16; o > 0; o >>= 1) tm = fmaxf(tm, __shfl_xor_sync(0xffffffffu, tm, o));
            float mn = fmaxf(m[qi], tm);
            float corr = __expf(m[qi] - mn);
            float p = valid ? __expf(sv - mn) : 0.f;
            float rs = p;
#pragma unroll
            for (int o = 16; o > 0; o >>= 1) rs += __shfl_xor_sync(0xffffffffu, rs, o);
            l[qi] = l[qi] * corr + rs;
            m[qi] = mn;
#pragma unroll
            for (int d = 0; d < 4; d++) acc[qi][d] *= corr;
            p_s[(w * 4 + qi) * 32 + lane] = p;
        }
        __syncwarp();

#pragma unroll 4
        for (int j = 0; j < 32; j++) {
            float4 vv = *(const float4*)&v_s[j * 132 + lane * 4];
#pragma unroll
            for (int qi = 0; qi < 4; qi++) {
                float p = p_s[(w * 4 + qi) * 32 + j];
                acc[qi][0] += p * vv.x;
                acc[qi][1] += p * vv.y;
                acc[qi][2] += p * vv.z;
                acc[qi][3] += p * vv.w;
            }
        }
    }

#pragma unroll
    for (int qi = 0; qi < 4; qi++) {
        int s = w * 4 + qi;
        *(float4*)&g_pacc[(pbase + s) * HDIM + lane * 4] =
            make_float4(acc[qi][0], acc[qi][1], acc[qi][2], acc[qi][3]);
        if (lane == 0) {
            g_pm[pbase + s] = m[qi];
            g_pl[pbase + s] = l[qi];
        }
    }
}

// ---------------------------------------------------------------------------
// Kernel 5: combine partials -> out
// ---------------------------------------------------------------------------
__global__ __launch_bounds__(128) void attn_combine(float* __restrict__ out) {
    const int bh = blockIdx.x;
    const int b = bh >> 5;
    const int h = bh & 31;
    const int d = threadIdx.x;

    for (int s = 0; s < SS; s++) {
        float mv[NSPLIT];
        float M = -1e30f;
#pragma unroll
        for (int c = 0; c < NSPLIT; c++) {
            mv[c] = g_pm[(c * BB * HH + bh) * SS + s];
            M = fmaxf(M, mv[c]);
        }
        float denom = 0.f, o = 0.f;
#pragma unroll
        for (int c = 0; c < NSPLIT; c++) {
            float wgt = __expf(mv[c] - M);
            denom += wgt * g_pl[(c * BB * HH + bh) * SS + s];
            o += wgt * g_pacc[((c * BB * HH + bh) * SS + s) * HDIM + d];
        }
        out[(b * SS + s) * DD + h * HDIM + d] = o / denom;
    }
}

// ---------------------------------------------------------------------------
extern "C" void kernel_launch(void* const* d_in, const int* in_sizes, int n_in,
                              void* d_out, int out_size) {
    const float* Q = (const float*)d_in[0];
    const float* K = (const float*)d_in[1];
    const float* V = (const float*)d_in[2];
    const float* Kcache = (const float*)d_in[3];
    const float* Vcache = (const float*)d_in[4];
    const float* w0 = (const float*)d_in[5];
    const float* w1 = (const float*)d_in[6];
    const float* w2 = (const float*)d_in[7];
    const float* emb = (const float*)d_in[8];
    const int* Cp = (const int*)d_in[9];

    float* out = (float*)d_out;
    float* okc = out + (size_t)BB * SS * DD;
    float* ovc = okc + (size_t)BB * HH * MAXLEN * HDIM;

    static cudaStream_t s2 = nullptr;
    static cudaEvent_t ev_fork = nullptr, ev_join = nullptr;
    if (s2 == nullptr) {
        cudaStreamCreateWithFlags(&s2, cudaStreamNonBlocking);
        cudaEventCreateWithFlags(&ev_fork, cudaEventDisableTiming);
        cudaEventCreateWithFlags(&ev_join, cudaEventDisableTiming);
        cudaFuncSetAttribute(gemm_tf32, cudaFuncAttributeMaxDynamicSharedMemorySize,
                             GEMM_SMEM_BYTES);
        cudaFuncSetAttribute(attn_partial, cudaFuncAttributeMaxDynamicSharedMemorySize,
                             ATTN_SMEM_BYTES);
    }

    // Compute chain starts: conv_x first (memory-bound, short).
    dim3 gx((512 * 4096 + 255) / 256, 3);
    conv_x<<<gx, 256>>>(Q, K, V);

    // Fork AFTER conv_x: tail copy (DRAM-bound) runs concurrently with the
    // gemm (compute-bound, DRAM ~10%) — the only pairing where overlap wins.
    cudaEventRecord(ev_fork, 0);
    cudaStreamWaitEvent(s2, ev_fork, 0);
    copy_tail<<<8192, 128, 0, s2>>>((const float4*)Kcache, (const float4*)Vcache,
                                    (float4*)okc, (float4*)ovc, Cp);

    dim3 gg(4096 / 128, 512 / 128, 3);
    gemm_tf32<<<gg, 256, GEMM_SMEM_BYTES>>>(w0, w1, w2);

    rope_scatter<<<(BB * SS * HH * 64 + 255) / 256, 256>>>(emb, Cp, okc, ovc);

    dim3 ga(BB * HH, NSPLIT);
    attn_partial<<<ga, 128, ATTN_SMEM_BYTES>>>(Kcache, Vcache, Cp, okc, ovc);
    attn_combine<<<BB * HH, 128>>>(out);

    // Join.
    cudaEventRecord(ev_join, s2);
    cudaStreamWaitEvent(0, ev_join, 0);
}

// round 15
// speedup vs baseline: 1.2382x; 1.0247x over previous
#include <cuda_runtime.h>
#include <cuda_bf16.h>
#include <cstdint>

#define BB 32
#define SS 16
#define DD 4096
#define HH 32
#define HDIM 128
#define MAXLEN 2048
#define NSPLIT 8

// Scratch
__device__ float g_qkv[3][512 * 4096];        // projection outputs (25 MB)
__device__ float g_xc[3][512 * 4096];         // rna(tf32) X, permuted-k (25 MB)
__device__ float g_knew[BB * HH * SS * HDIM]; // roped new K rows (8.4 MB)
__device__ float g_vnew[BB * HH * SS * HDIM]; // new V rows (8.4 MB)
__device__ float g_pm[NSPLIT * BB * HH * SS];
__device__ float g_pl[NSPLIT * BB * HH * SS];
__device__ float g_pacc[NSPLIT * BB * HH * SS * HDIM];

__device__ __forceinline__ float to_tf32(float x) {
    uint32_t u;
    asm("cvt.rna.tf32.f32 %0, %1;" : "=r"(u) : "f"(x));
    return __uint_as_float(u);
}
__device__ __forceinline__ uint32_t smem_u32(const void* p) {
    uint32_t a;
    asm("{ .reg .u64 t; cvta.to.shared.u64 t, %1; cvt.u32.u64 %0, t; }" : "=r"(a) : "l"(p));
    return a;
}
// logical k held at permuted column c (within 8-groups: [0,4,1,5,2,6,3,7])
__device__ __forceinline__ int kperm(int c) {
    return (c & ~7) | ((c & 7) >> 1) | ((c & 1) << 2);
}

// ---------------------------------------------------------------------------
// Kernel 0: X -> g_xc[z][m][c] = rna(X[m][kperm(c)])
// ---------------------------------------------------------------------------
__global__ __launch_bounds__(256) void conv_x(
    const float* __restrict__ Q, const float* __restrict__ K, const float* __restrict__ V) {
    const int z = blockIdx.y;
    const float* X = (z == 0) ? Q : ((z == 1) ? K : V);
    int idx = blockIdx.x * 256 + threadIdx.x;
    if (idx >= 512 * 4096) return;
    int m = idx >> 12, c = idx & 4095;
    g_xc[z][idx] = to_tf32(X[(size_t)m * 4096 + kperm(c)]);
}

// ---------------------------------------------------------------------------
// Kernel 2: tf32 mma.sync GEMM, cp.async 3-stage, WITH embedded tail-cache
// copy duty. Each of 384 CTAs copies its 1/384 slice of cache rows
// [L, MAXLEN), ~672 float4 per k-iteration, loads issued before the MMA
// block (latency hidden under compute), stores after.
// A from g_xc (tf32, permuted, (m,k) stride 36, LDS.64 pairs). B from raw W,
// native (k,n) layout, stride 136, cvt.rna on fragment registers.
// BM=BN=128, BK=32, 8 warps, warp 64x32.
// ---------------------------------------------------------------------------
#define ASTRIDE 36
#define BSTRIDE 136
#define ATILEF (128 * ASTRIDE)
#define BTILEF (32 * BSTRIDE)
#define STAGEF (ATILEF + BTILEF)
#define GEMM_SMEM_BYTES (3 * STAGEF * 4)   // 107520
#define NCTA 384

__global__ __launch_bounds__(256) void gemm_tf32(
    const float* __restrict__ w0, const float* __restrict__ w1, const float* __restrict__ w2,
    const float4* __restrict__ kc4, const float4* __restrict__ vc4,
    float4* __restrict__ okc4, float4* __restrict__ ovc4,
    const int* __restrict__ Cp) {
    extern __shared__ float sm[];
    const uint32_t sb = smem_u32(sm);
    const int z = blockIdx.z;
    const float* A = g_xc[z];
    const float* W = (z == 0) ? w0 : ((z == 1) ? w1 : w2);
    float* Cout = g_qkv[z];

    const int m0 = blockIdx.y * 128;
    const int n0 = blockIdx.x * 128;
    const int tid = threadIdx.x;
    const int wid = tid >> 5;
    const int lane = tid & 31;
    const int g = lane >> 2;
    const int t = lane & 3;
    const int warp_m = (wid & 1) * 64;
    const int warp_n = (wid >> 1) * 32;

    // ---- tail-copy slice for this CTA ----
    const int L = Cp[0] + SS;
    const int tail_grp = (MAXLEN - L) * 32;              // float4 per (b,h)
    const int tail_total = tail_grp * BB * HH;           // float4 per cache
    const int per_cta = (tail_total + NCTA - 1) / NCTA;
    const int per_it = (per_cta + 127) / 128;            // ~672
    const int cta_id = (blockIdx.z * 4 + blockIdx.y) * 32 + blockIdx.x;
    const int cbase = cta_id * per_cta;
    const int cend_cta = min(cbase + per_cta, tail_total);

    float c[4][4][4];
#pragma unroll
    for (int mf = 0; mf < 4; mf++)
#pragma unroll
        for (int nf = 0; nf < 4; nf++)
#pragma unroll
            for (int r = 0; r < 4; r++) c[mf][nf][r] = 0.f;

    auto copy_tile = [&](int s, int k0) {
#pragma unroll
        for (int j = 0; j < 4; j++) {
            int idx = tid + j * 256;
            int r = idx >> 3, c4 = idx & 7;
            uint32_t dst = sb + (uint32_t)(s * STAGEF + r * ASTRIDE + c4 * 4) * 4;
            const float* src = &A[(size_t)(m0 + r) * 4096 + k0 + c4 * 4];
            asm volatile("cp.async.cg.shared.global [%0], [%1], 16;" :: "r"(dst), "l"(src));
        }
#pragma unroll
        for (int j = 0; j < 4; j++) {
            int idx = tid + j * 256;
            int r = idx >> 5, c4 = idx & 31;
            uint32_t dst = sb + (uint32_t)(s * STAGEF + ATILEF + r * BSTRIDE + c4 * 4) * 4;
            const float* src = &W[(size_t)(k0 + r) * 4096 + n0 + c4 * 4];
            asm volatile("cp.async.cg.shared.global [%0], [%1], 16;" :: "r"(dst), "l"(src));
        }
        asm volatile("cp.async.commit_group;");
    };

    auto compute = [&](int s) {
        const float* As = sm + s * STAGEF;
        const float* Bs = As + ATILEF;
#pragma unroll
        for (int ks = 0; ks < 4; ks++) {
            const int kb = ks * 8;
            uint32_t a[4][4], b[4][2];
#pragma unroll
            for (int mf = 0; mf < 4; mf++) {
                int r0 = warp_m + mf * 16 + g;
                uint2 lo = *(const uint2*)&As[r0 * ASTRIDE + kb + 2 * t];
                uint2 hi = *(const uint2*)&As[(r0 + 8) * ASTRIDE + kb + 2 * t];
                a[mf][0] = lo.x; a[mf][1] = hi.x; a[mf][2] = lo.y; a[mf][3] = hi.y;
            }
#pragma unroll
            for (int nf = 0; nf < 4; nf++) {
                int n = warp_n + nf * 8 + g;
                b[nf][0] = __float_as_uint(to_tf32(Bs[(kb + t) * BSTRIDE + n]));
                b[nf][1] = __float_as_uint(to_tf32(Bs[(kb + t + 4) * BSTRIDE + n]));
            }
#pragma unroll
            for (int mf = 0; mf < 4; mf++)
#pragma unroll
                for (int nf = 0; nf < 4; nf++) {
                    asm volatile(
                        "mma.sync.aligned.m16n8k8.row.col.f32.tf32.tf32.f32 "
                        "{%0,%1,%2,%3}, {%4,%5,%6,%7}, {%8,%9}, {%0,%1,%2,%3};"
                        : "+f"(c[mf][nf][0]), "+f"(c[mf][nf][1]),
                          "+f"(c[mf][nf][2]), "+f"(c[mf][nf][3])
                        : "r"(a[mf][0]), "r"(a[mf][1]), "r"(a[mf][2]), "r"(a[mf][3]),
                          "r"(b[nf][0]), "r"(b[nf][1]));
                }
        }
    };

    copy_tile(0, 0);
    copy_tile(1, 32);

    for (int it = 0; it < 128; ++it) {
        if (it < 126)
            asm volatile("cp.async.wait_group 1;");
        else
            asm volatile("cp.async.wait_group 0;");
        __syncthreads();

        // ---- tail-copy: issue loads (latency hides under the MMA block) ----
        float4 rk[4], rv[4];
        int offs[4];
        int nel = 0;
        {
            int cb = cbase + it * per_it;
            int ce = min(cb + per_it, cend_cta);
            for (int i = cb + tid; i < ce && nel < 4; i += 256) {
                int bh = i / tail_grp;
                int rem = i - bh * tail_grp;
                int off = (bh * MAXLEN + L) * 32 + rem;   // rows contiguous after L
                rk[nel] = __ldcs(&kc4[off]);
                rv[nel] = __ldcs(&vc4[off]);
                offs[nel] = off;
                nel++;
            }
        }

        compute(it % 3);
        if (it + 2 < 128) copy_tile((it + 2) % 3, (it + 2) * 32);

        // ---- tail-copy: drain stores ----
        for (int j = 0; j < nel; j++) {
            __stcs(&okc4[offs[j]], rk[j]);
            __stcs(&ovc4[offs[j]], rv[j]);
        }
    }

#pragma unroll
    for (int mf = 0; mf < 4; mf++) {
        int row = m0 + warp_m + mf * 16 + g;
#pragma unroll
        for (int nf = 0; nf < 4; nf++) {
            int col = n0 + warp_n + nf * 8 + t * 2;
            *(float2*)&Cout[(size_t)row * 4096 + col] =
                make_float2(c[mf][nf][0], c[mf][nf][1]);
            *(float2*)&Cout[(size_t)(row + 8) * 4096 + col] =
                make_float2(c[mf][nf][2], c[mf][nf][3]);
        }
    }
}

// ---------------------------------------------------------------------------
// Kernel 3: RoPE q in place; rope k / copy v -> okc/ovc rows AND g_knew/g_vnew
// ---------------------------------------------------------------------------
__global__ void rope_scatter(const float* __restrict__ emb, const int* __restrict__ Cp,
                             float* __restrict__ okc, float* __restrict__ ovc) {
    int idx = blockIdx.x * blockDim.x + threadIdx.x;
    if (idx >= BB * SS * HH * 64) return;
    int e = idx & 63;
    int h = (idx >> 6) & 31;
    int s = (idx >> 11) & 15;
    int b = idx >> 15;
    int Cv = Cp[0];

    float c = emb[s * HDIM + e];
    float sn = emb[SS * HDIM + s * HDIM + e];
    int row = b * SS + s;
    int c1 = h * HDIM + e;
    int c2 = c1 + 64;

    float* qp = g_qkv[0];
    float x1 = qp[row * DD + c1], x2 = qp[row * DD + c2];
    qp[row * DD + c1] = x1 * c - x2 * sn;
    qp[row * DD + c2] = x2 * c + x1 * sn;

    const float* kp = g_qkv[1];
    x1 = kp[row * DD + c1];
    x2 = kp[row * DD + c2];
    float k1 = x1 * c - x2 * sn;
    float k2 = x2 * c + x1 * sn;
    int o = ((b * HH + h) * MAXLEN + (Cv + s)) * HDIM;
    int on = ((b * HH + h) * SS + s) * HDIM;
    okc[o + e] = k1;
    okc[o + e + 64] = k2;
    g_knew[on + e] = k1;
    g_knew[on + e + 64] = k2;

    const float* vp = g_qkv[2];
    float v1 = vp[row * DD + c1];
    float v2 = vp[row * DD + c2];
    ovc[o + e] = v1;
    ovc[o + e + 64] = v2;
    g_vnew[on + e] = v1;
    g_vnew[on + e + 64] = v2;
}

// ---------------------------------------------------------------------------
// Kernel 4: split-K flash attention partials + copy duty for rows [0,C).
// K/V read from INPUT caches (pos < C) / g_knew,g_vnew (pos >= C) via
// double-buffered cp.async; after each tile lands in smem, rows with
// kpos < C are stored to okc/ovc (the chunks tile [0,L) disjointly).
// ---------------------------------------------------------------------------
#define QF (SS * 132)                 // 2112 floats
#define KVF (32 * 132)                // 4224 floats per k/v buffer
#define ATTN_SMEM_F (QF + 4 * KVF + 4 * 4 * 32)
#define ATTN_SMEM_BYTES (ATTN_SMEM_F * 4)   // 78080

__global__ __launch_bounds__(128) void attn_partial(
    const float* __restrict__ Kcin, const float* __restrict__ Vcin,
    const int* __restrict__ Cp,
    float* __restrict__ okc, float* __restrict__ ovc) {
    extern __shared__ float dsm[];
    float* q_s = dsm;                       // [16][132]
    float* p_s = dsm + QF + 4 * KVF;        // [4][4][32]
    const uint32_t sb = smem_u32(dsm);

    const int tid = threadIdx.x;
    const int w = tid >> 5;
    const int lane = tid & 31;
    const int bh = blockIdx.x;
    const int chunk = blockIdx.y;
    const int b = bh >> 5;
    const int h = bh & 31;
    const int Cv = Cp[0];
    const int L = Cv + SS;
    const int csz = (((L + NSPLIT - 1) / NSPLIT) + 31) & ~31;
    const int kstart = chunk * csz;
    const int kend = min(kstart + csz, L);
    const int pbase = (chunk * BB * HH + bh) * SS;

    if (kstart >= kend) {
        for (int i = tid; i < SS * HDIM; i += 128) g_pacc[pbase * HDIM + i] = 0.f;
        if (tid < SS) {
            g_pm[pbase + tid] = -1e30f;
            g_pl[pbase + tid] = 0.f;
        }
        return;
    }

    // q tile
    const float* qbase = g_qkv[0] + (b * SS) * DD + h * HDIM;
    for (int i = tid; i < SS * 32; i += 128) {
        int r = i >> 5, c4 = i & 31;
        *(float4*)&q_s[r * 132 + c4 * 4] = *(const float4*)&qbase[r * DD + c4 * 4];
    }

    const float* kold = Kcin + (size_t)bh * MAXLEN * HDIM;
    const float* vold = Vcin + (size_t)bh * MAXLEN * HDIM;
    const float* knew = g_knew + (size_t)bh * SS * HDIM;
    const float* vnew = g_vnew + (size_t)bh * SS * HDIM;
    float* kout = okc + (size_t)bh * MAXLEN * HDIM;
    float* vout = ovc + (size_t)bh * MAXLEN * HDIM;

    auto load_tile = [&](int base, int buf) {
        uint32_t kdst = sb + (uint32_t)(QF + buf * 2 * KVF) * 4;
        uint32_t vdst = kdst + (uint32_t)KVF * 4;
#pragma unroll
        for (int j = 0; j < 8; j++) {
            int idx = tid + j * 128;
            int r = idx >> 5, c4 = idx & 31;
            int kpos = base + r;
            uint32_t off = (uint32_t)(r * 132 + c4 * 4) * 4;
            if (kpos < Cv) {
                const float* sk = &kold[(size_t)kpos * HDIM + c4 * 4];
                const float* sv = &vold[(size_t)kpos * HDIM + c4 * 4];
                asm volatile("cp.async.cg.shared.global [%0], [%1], 16;" :: "r"(kdst + off), "l"(sk));
                asm volatile("cp.async.cg.shared.global [%0], [%1], 16;" :: "r"(vdst + off), "l"(sv));
            } else if (kpos < kend) {
                const float* sk = &knew[(size_t)(kpos - Cv) * HDIM + c4 * 4];
                const float* sv = &vnew[(size_t)(kpos - Cv) * HDIM + c4 * 4];
                asm volatile("cp.async.cg.shared.global [%0], [%1], 16;" :: "r"(kdst + off), "l"(sk));
                asm volatile("cp.async.cg.shared.global [%0], [%1], 16;" :: "r"(vdst + off), "l"(sv));
            } else {
                float* vp = dsm + QF + (buf * 2 + 1) * KVF + r * 132 + c4 * 4;
                *(float4*)vp = make_float4(0.f, 0.f, 0.f, 0.f);
            }
        }
        asm volatile("cp.async.commit_group;");
    };

    float m[4], l[4], acc[4][4];
#pragma unroll
    for (int qi = 0; qi < 4; qi++) {
        m[qi] = -1e30f;
        l[qi] = 0.f;
#pragma unroll
        for (int d = 0; d < 4; d++) acc[qi][d] = 0.f;
    }

    const int nt = (kend - kstart + 31) / 32;
    load_tile(kstart, 0);

    for (int tix = 0; tix < nt; tix++) {
        asm volatile("cp.async.wait_group 0;");
        __syncthreads();
        const int buf = tix & 1;
        if (tix + 1 < nt) load_tile(kstart + (tix + 1) * 32, buf ^ 1);

        const float* k_s = dsm + QF + buf * 2 * KVF;
        const float* v_s = k_s + KVF;
        const int base = kstart + tix * 32;

        // copy duty: write old-cache rows of this tile to the output caches
        if (base < Cv) {
#pragma unroll
            for (int j = 0; j < 8; j++) {
                int idx = tid + j * 128;
                int r = idx >> 5, c4 = idx & 31;
                int kpos = base + r;
                if (kpos < Cv) {
                    float4 kv = *(const float4*)&k_s[r * 132 + c4 * 4];
                    float4 vv = *(const float4*)&v_s[r * 132 + c4 * 4];
                    __stcs((float4*)&kout[(size_t)kpos * HDIM + c4 * 4], kv);
                    __stcs((float4*)&vout[(size_t)kpos * HDIM + c4 * 4], vv);
                }
            }
        }

        float sc[4] = {0.f, 0.f, 0.f, 0.f};
#pragma unroll 8
        for (int d4 = 0; d4 < 32; d4++) {
            float4 kv = *(const float4*)&k_s[lane * 132 + d4 * 4];
#pragma unroll
            for (int qi = 0; qi < 4; qi++) {
                float4 qv = *(const float4*)&q_s[(w * 4 + qi) * 132 + d4 * 4];
                sc[qi] += qv.x * kv.x + qv.y * kv.y + qv.z * kv.z + qv.w * kv.w;
            }
        }

        int kpos = base + lane;
#pragma unroll
        for (int qi = 0; qi < 4; qi++) {
            bool valid = (kpos < kend) && (kpos <= Cv + (w * 4 + qi));
            float sv = valid ? sc[qi] * 0.08838834764831845f : -1e30f;
            float tm = sv;
#pragma unroll
            for (int o = 16; o > 0; o >>= 1) tm = fmaxf(tm, __shfl_xor_sync(0xffffffffu, tm, o));
            float mn = fmaxf(m[qi], tm);
            float corr = __expf(m[qi] - mn);
            float p = valid ? __expf(sv - mn) : 0.f;
            float rs = p;
#pragma unroll
            for (int o = 16; o > 0; o >>= 1) rs += __shfl_xor_sync(0xffffffffu, rs, o);
            l[qi] = l[qi] * corr + rs;
            m[qi] = mn;
#pragma unroll
            for (int d = 0; d < 4; d++) acc[qi][d] *= corr;
            p_s[(w * 4 + qi) * 32 + lane] = p;
        }
        __syncwarp();

#pragma unroll 4
        for (int j = 0; j < 32; j++) {
            float4 vv = *(const float4*)&v_s[j * 132 + lane * 4];
#pragma unroll
            for (int qi = 0; qi < 4; qi++) {
                float p = p_s[(w * 4 + qi) * 32 + j];
                acc[qi][0] += p * vv.x;
                acc[qi][1] += p * vv.y;
                acc[qi][2] += p * vv.z;
                acc[qi][3] += p * vv.w;
            }
        }
    }

#pragma unroll
    for (int qi = 0; qi < 4; qi++) {
        int s = w * 4 + qi;
        *(float4*)&g_pacc[(pbase + s) * HDIM + lane * 4] =
            make_float4(acc[qi][0], acc[qi][1], acc[qi][2], acc[qi][3]);
        if (lane == 0) {
            g_pm[pbase + s] = m[qi];
            g_pl[pbase + s] = l[qi];
        }
    }
}

// ---------------------------------------------------------------------------
// Kernel 5: combine partials -> out
// ---------------------------------------------------------------------------
__global__ __launch_bounds__(128) void attn_combine(float* __restrict__ out) {
    const int bh = blockIdx.x;
    const int b = bh >> 5;
    const int h = bh & 31;
    const int d = threadIdx.x;

    for (int s = 0; s < SS; s++) {
        float mv[NSPLIT];
        float M = -1e30f;
#pragma unroll
        for (int c = 0; c < NSPLIT; c++) {
            mv[c] = g_pm[(c * BB * HH + bh) * SS + s];
            M = fmaxf(M, mv[c]);
        }
        float denom = 0.f, o = 0.f;
#pragma unroll
        for (int c = 0; c < NSPLIT; c++) {
            float wgt = __expf(mv[c] - M);
            denom += wgt * g_pl[(c * BB * HH + bh) * SS + s];
            o += wgt * g_pacc[((c * BB * HH + bh) * SS + s) * HDIM + d];
        }
        out[(b * SS + s) * DD + h * HDIM + d] = o / denom;
    }
}

// ---------------------------------------------------------------------------
extern "C" void kernel_launch(void* const* d_in, const int* in_sizes, int n_in,
                              void* d_out, int out_size) {
    const float* Q = (const float*)d_in[0];
    const float* K = (const float*)d_in[1];
    const float* V = (const float*)d_in[2];
    const float* Kcache = (const float*)d_in[3];
    const float* Vcache = (const float*)d_in[4];
    const float* w0 = (const float*)d_in[5];
    const float* w1 = (const float*)d_in[6];
    const float* w2 = (const float*)d_in[7];
    const float* emb = (const float*)d_in[8];
    const int* Cp = (const int*)d_in[9];

    float* out = (float*)d_out;
    float* okc = out + (size_t)BB * SS * DD;
    float* ovc = okc + (size_t)BB * HH * MAXLEN * HDIM;

    static bool init = false;
    if (!init) {
        init = true;
        cudaFuncSetAttribute(gemm_tf32, cudaFuncAttributeMaxDynamicSharedMemorySize,
                             GEMM_SMEM_BYTES);
        cudaFuncSetAttribute(attn_partial, cudaFuncAttributeMaxDynamicSharedMemorySize,
                             ATTN_SMEM_BYTES);
    }

    dim3 gx((512 * 4096 + 255) / 256, 3);
    conv_x<<<gx, 256>>>(Q, K, V);

    dim3 gg(4096 / 128, 512 / 128, 3);
    gemm_tf32<<<gg, 256, GEMM_SMEM_BYTES>>>(w0, w1, w2,
                                            (const float4*)Kcache, (const float4*)Vcache,
                                            (float4*)okc, (float4*)ovc, Cp);

    rope_scatter<<<(BB * SS * HH * 64 + 255) / 256, 256>>>(emb, Cp, okc, ovc);

    dim3 ga(BB * HH, NSPLIT);
    attn_partial<<<ga, 128, ATTN_SMEM_BYTES>>>(Kcache, Vcache, Cp, okc, ovc);
    attn_combine<<<BB * HH, 128>>>(out);
}